// round 13
// baseline (speedup 1.0000x reference)
#include <cuda_runtime.h>
#include <cuda_fp16.h>
#include <math.h>
#include <stdint.h>

#define M_TOT 8192
#define C_DIM 1024
#define S_LEN 2048
#define NB 4

// ---------------- static scratch (no allocations allowed) ----------------
// fp32
__device__ float g_h0[M_TOT * C_DIM];
__device__ float g_att[M_TOT * C_DIM];
__device__ float g_pred[M_TOT * C_DIM];
// fp16 buffers
#define W_FCIN 0
#define W_QKV  1048576
#define W_PROJ 13631488
#define W_FCOUT 17825792
#define W_TOTAL 18874368
__device__ __half g_w_h[W_TOTAL];
__device__ __half g_x_h[M_TOT * C_DIM];
__device__ __half g_a_h[M_TOT * C_DIM];
__device__ __half g_qkv_h[(long)M_TOT * 3 * C_DIM];
__device__ __half g_kt_h[(long)NB * C_DIM * S_LEN];
__device__ __half g_vt_h[(long)NB * C_DIM * S_LEN];
__device__ __half g_m1_h[(long)NB * C_DIM * C_DIM];
__device__ __half g_sm_h[M_TOT * C_DIM];

// ---------------- helpers ----------------
__device__ __forceinline__ uint32_t smem_u32(const void* p) {
    uint32_t a;
    asm("{ .reg .u64 t; cvta.to.shared.u64 t, %1; cvt.u32.u64 %0, t; }" : "=r"(a) : "l"(p));
    return a;
}
__device__ __forceinline__ float gelu_f(float x) {
    return 0.5f * x * (1.0f + erff(x * 0.70710678118654752f));
}
__device__ __forceinline__ uint32_t h2_bits(__half2 v) {
    return *reinterpret_cast<uint32_t*>(&v);
}
__device__ __forceinline__ void ldsm4(uint32_t* r, uint32_t addr) {
    asm volatile("ldmatrix.sync.aligned.m8n8.x4.shared.b16 {%0,%1,%2,%3}, [%4];"
        : "=r"(r[0]), "=r"(r[1]), "=r"(r[2]), "=r"(r[3]) : "r"(addr));
}
__device__ __forceinline__ void mma16816(float* d, const uint32_t* a, const uint32_t* b) {
    asm volatile("mma.sync.aligned.m16n8k16.row.col.f32.f16.f16.f32 "
        "{%0,%1,%2,%3}, {%4,%5,%6,%7}, {%8,%9}, {%0,%1,%2,%3};"
        : "+f"(d[0]), "+f"(d[1]), "+f"(d[2]), "+f"(d[3])
        : "r"(a[0]), "r"(a[1]), "r"(a[2]), "r"(a[3]), "r"(b[0]), "r"(b[1]));
}
#define CP16(dst, src) \
    asm volatile("cp.async.cg.shared.global [%0], [%1], 16;" :: "r"(dst), "l"(src) : "memory")
#define CP_COMMIT() asm volatile("cp.async.commit_group;" ::: "memory")
#define CP_WAIT1() asm volatile("cp.async.wait_group 1;" ::: "memory")

// SMEM stage: A tile + B tile, each 128 rows x 64 fp16 (128B), row stride 144B.
#define ROW_B 144
#define OFF_A 0
#define OFF_B 18432
#define STAGE_B 36864
#define SM_TOT (2 * STAGE_B)

// D[M,N] = epi(scale * A[M,K] @ B[N,K]^T), fp16 inputs, single-pass HMMA,
// 2-stage cp.async, BK=64. CTA 128x128, 256 thr = 8 warps (2M x 4N), warp 64x32.
__global__ void __launch_bounds__(256, 2) gemm_fp16(
    const __half* __restrict__ A, const __half* __restrict__ B,
    float* __restrict__ C, __half* __restrict__ O,
    int K, int lda, int ldb, int ldc,
    long sA, long sB, long sC,
    const float* __restrict__ bias, const float* __restrict__ residual,
    float scale, int act, int pe)
{
    extern __shared__ char sm[];
    uint32_t sb = smem_u32(sm);

    int tid = threadIdx.x, wid = tid >> 5, lane = tid & 31;
    long bz = blockIdx.z;
    A += bz * sA; B += bz * sB;
    if (C) C += bz * sC;
    if (O) O += bz * sC;
    const float* res = residual ? residual + bz * sC : nullptr;
    long row0 = (long)blockIdx.y * 128, col0 = (long)blockIdx.x * 128;

    int wm = wid >> 2, wn = wid & 3;     // 2 x 4 warp grid
    int m0w = wm * 64, n0w = wn * 32;

    float acc[4][4][4];
#pragma unroll
    for (int i = 0; i < 4; i++)
#pragma unroll
        for (int j = 0; j < 4; j++)
#pragma unroll
            for (int e = 0; e < 4; e++) acc[i][j][e] = 0.f;

    // loader: row = tid>>1 (0..127), 64B half hf = tid&1; 4 CP16 per tile per chunk
    const int r_ld = tid >> 1;
    const int hf = tid & 1;
    const int NC = K >> 6;

    const __half* a_src = A + (row0 + r_ld) * lda + hf * 32;
    const __half* b_src = B + (col0 + r_ld) * ldb + hf * 32;
    const uint32_t stA = sb + OFF_A + r_ld * ROW_B + hf * 64;
    const uint32_t stB = sb + OFF_B + r_ld * ROW_B + hf * 64;

    auto issue = [&](int c, uint32_t bofs) {
        long ko = (long)c * 64;
        CP16(stA + bofs,      a_src + ko);
        CP16(stA + bofs + 16, a_src + ko + 8);
        CP16(stA + bofs + 32, a_src + ko + 16);
        CP16(stA + bofs + 48, a_src + ko + 24);
        CP16(stB + bofs,      b_src + ko);
        CP16(stB + bofs + 16, b_src + ko + 8);
        CP16(stB + bofs + 32, b_src + ko + 16);
        CP16(stB + bofs + 48, b_src + ko + 24);
    };

    // ldmatrix addresses (stage 0 base; add bofs, + ks*32 per k16 step)
    uint32_t a_addr[4], b_addr[2];
#pragma unroll
    for (int i = 0; i < 4; i++) {
        uint32_t r = m0w + i * 16 + (lane & 15);
        a_addr[i] = sb + OFF_A + r * ROW_B + (lane >> 4) * 16;
    }
#pragma unroll
    for (int jp = 0; jp < 2; jp++) {     // pair of n-tiles (2jp, 2jp+1)
        uint32_t r = n0w + jp * 16 + ((lane >> 4) << 3) + (lane & 7);
        b_addr[jp] = sb + OFF_B + r * ROW_B + ((lane >> 3) & 1) * 16;
    }

    issue(0, 0); CP_COMMIT();
    if (NC > 1) issue(1, STAGE_B);
    CP_COMMIT();

    for (int c = 0; c < NC; c++) {
        CP_WAIT1();
        __syncthreads();
        uint32_t bofs = (c & 1) * STAGE_B;
#pragma unroll
        for (int ks = 0; ks < 4; ks++) {
            uint32_t ah[4][4], bh[2][4];
#pragma unroll
            for (int i = 0; i < 4; i++)
                ldsm4(ah[i], a_addr[i] + bofs + ks * 32);
#pragma unroll
            for (int jp = 0; jp < 2; jp++)
                ldsm4(bh[jp], b_addr[jp] + bofs + ks * 32);
#pragma unroll
            for (int i = 0; i < 4; i++)
#pragma unroll
                for (int j = 0; j < 4; j++)
                    mma16816(acc[i][j], ah[i], &bh[j >> 1][(j & 1) * 2]);
        }
        __syncthreads();
        if (c + 2 < NC) issue(c + 2, (c & 1) * STAGE_B);
        CP_COMMIT();
    }

    // epilogue: thread holds C[r1][cc..cc+1], C[r1+8][cc..cc+1] per (i,j)
#pragma unroll
    for (int i = 0; i < 4; i++) {
        long r1 = row0 + m0w + i * 16 + (lane >> 2);
        long r2 = r1 + 8;
#pragma unroll
        for (int j = 0; j < 4; j++) {
            long cc = col0 + n0w + j * 8 + 2 * (lane & 3);
            float2 bi = bias ? *(const float2*)(bias + cc) : make_float2(0.f, 0.f);
            float v0 = acc[i][j][0] * scale + bi.x;
            float v1 = acc[i][j][1] * scale + bi.y;
            float v2 = acc[i][j][2] * scale + bi.x;
            float v3 = acc[i][j][3] * scale + bi.y;
            if (act) { v0 = gelu_f(v0); v1 = gelu_f(v1); v2 = gelu_f(v2); v3 = gelu_f(v3); }
            if (res) {
                float2 q1 = *(const float2*)(res + r1 * ldc + cc);
                float2 q2 = *(const float2*)(res + r2 * ldc + cc);
                v0 += q1.x; v1 += q1.y; v2 += q2.x; v3 += q2.y;
            }
            if (pe) {
                float d0 = expf((float)cc * (-2.0f / 1024.0f) * 6.9077552789821370521f);
                float d1 = expf((float)(cc + 1) * (-2.0f / 1024.0f) * 6.9077552789821370521f);
                int s1 = (int)(r1 & (S_LEN - 1)), s2 = (int)(r2 & (S_LEN - 1));
                float a10 = s1 * d0, a11 = s1 * d1, a20 = s2 * d0, a21 = s2 * d1;
                v0 += (s1 & 1) ? cosf(a10) : sinf(a10);
                v1 += (s1 & 1) ? cosf(a11) : sinf(a11);
                v2 += (s2 & 1) ? cosf(a20) : sinf(a20);
                v3 += (s2 & 1) ? cosf(a21) : sinf(a21);
            }
            if (C) {
                *(float2*)(C + r1 * ldc + cc) = make_float2(v0, v1);
                *(float2*)(C + r2 * ldc + cc) = make_float2(v2, v3);
            }
            if (O) {
                *(uint32_t*)(O + r1 * ldc + cc) = h2_bits(__floats2half2_rn(v0, v1));
                *(uint32_t*)(O + r2 * ldc + cc) = h2_bits(__floats2half2_rn(v2, v3));
            }
        }
    }
}

// fused fp32 -> fp16 convert of 5 tensors, grid-stride over float4s
__global__ void cvt5_kernel(const float* s0, __half* d0, long n0,
                            const float* s1, __half* d1, long n1,
                            const float* s2, __half* d2, long n2,
                            const float* s3, __half* d3, long n3,
                            const float* s4, __half* d4, long n4)
{
    long tot = n0 + n1 + n2 + n3 + n4;
    long i = (long)blockIdx.x * blockDim.x + threadIdx.x;
    long stride = (long)gridDim.x * blockDim.x;
    for (; i < tot; i += stride) {
        const float* s; __half* d; long k = i;
        if (k < n0) { s = s0; d = d0; }
        else if ((k -= n0) < n1) { s = s1; d = d1; }
        else if ((k -= n1) < n2) { s = s2; d = d2; }
        else if ((k -= n2) < n3) { s = s3; d = d3; }
        else { k -= n3; s = s4; d = d4; }
        float4 f = ((const float4*)s)[k];
        uint2 h;
        h.x = h2_bits(__floats2half2_rn(f.x, f.y));
        h.y = h2_bits(__floats2half2_rn(f.z, f.w));
        ((uint2*)d)[k] = h;
    }
}

// dst[b][c][s] = qkv[b, s, co + c], vectorized 64x64 tile (uint4 both sides)
__global__ void transpose_h(const __half* __restrict__ q,
                            __half* __restrict__ dst_, int co)
{
    __shared__ __half t[64][65];
    int b = blockIdx.z;
    int s0 = blockIdx.x * 64, c0 = blockIdx.y * 64;
    int r = threadIdx.x >> 3;      // 0..31
    int g = threadIdx.x & 7;       // 0..7 (8-half group)
    const __half* src = q + (long)b * S_LEN * 3 * C_DIM + co;
#pragma unroll
    for (int rr = r; rr < 64; rr += 32) {
        uint4 v = *(const uint4*)(src + (long)(s0 + rr) * (3 * C_DIM) + c0 + g * 8);
        __half tmp[8];
        *(uint4*)tmp = v;
#pragma unroll
        for (int e = 0; e < 8; e++) t[rr][g * 8 + e] = tmp[e];
    }
    __syncthreads();
    __half* dst = dst_ + (long)b * C_DIM * S_LEN;
#pragma unroll
    for (int rr = r; rr < 64; rr += 32) {   // c index
        __half tmp[8];
#pragma unroll
        for (int e = 0; e < 8; e++) tmp[e] = t[g * 8 + e][rr];
        *(uint4*)(dst + (long)(c0 + rr) * S_LEN + s0 + g * 8) = *(uint4*)tmp;
    }
}

// layernorm over last dim (1024), fp32 in -> fp16 out
__global__ void layernorm_kernel(const float* __restrict__ h,
                                 const float* __restrict__ g,
                                 const float* __restrict__ b,
                                 __half* __restrict__ oh)
{
    __shared__ float sa[8], sb2[8];
    long row = blockIdx.x;
    const float* p = h + row * C_DIM;
    int tid = threadIdx.x;
    float v[4];
    float s1 = 0.f, s2 = 0.f;
#pragma unroll
    for (int i = 0; i < 4; i++) {
        v[i] = p[tid + i * 256];
        s1 += v[i];
        s2 += v[i] * v[i];
    }
#pragma unroll
    for (int o = 16; o > 0; o >>= 1) {
        s1 += __shfl_down_sync(0xffffffffu, s1, o);
        s2 += __shfl_down_sync(0xffffffffu, s2, o);
    }
    int lane = tid & 31, w = tid >> 5;
    if (lane == 0) { sa[w] = s1; sb2[w] = s2; }
    __syncthreads();
    if (tid < 32) {
        s1 = (tid < 8) ? sa[tid] : 0.f;
        s2 = (tid < 8) ? sb2[tid] : 0.f;
#pragma unroll
        for (int o = 4; o > 0; o >>= 1) {
            s1 += __shfl_down_sync(0xffffffffu, s1, o);
            s2 += __shfl_down_sync(0xffffffffu, s2, o);
        }
        if (tid == 0) { sa[0] = s1; sb2[0] = s2; }
    }
    __syncthreads();
    float mu = sa[0] * (1.0f / 1024.0f);
    float var = sb2[0] * (1.0f / 1024.0f) - mu * mu;
    float inv = rsqrtf(var + 1e-5f);
#pragma unroll
    for (int i = 0; i < 4; i++) {
        int c = tid + i * 256;
        float y = (v[i] - mu) * inv * g[c] + b[c];
        oh[row * C_DIM + c] = __float2half_rn(y);
    }
}

// softmax over last dim (1024), fp32 in -> fp16 out
__global__ void softmax_kernel(const float* __restrict__ att,
                               __half* __restrict__ oh)
{
    __shared__ float sh[8];
    long row = blockIdx.x;
    const float* p = att + row * C_DIM;
    int tid = threadIdx.x;
    float v[4];
    float m = -INFINITY;
#pragma unroll
    for (int i = 0; i < 4; i++) {
        v[i] = p[tid + i * 256];
        m = fmaxf(m, v[i]);
    }
#pragma unroll
    for (int o = 16; o > 0; o >>= 1)
        m = fmaxf(m, __shfl_down_sync(0xffffffffu, m, o));
    int lane = tid & 31, w = tid >> 5;
    if (lane == 0) sh[w] = m;
    __syncthreads();
    if (tid < 32) {
        m = (tid < 8) ? sh[tid] : -INFINITY;
#pragma unroll
        for (int o = 4; o > 0; o >>= 1)
            m = fmaxf(m, __shfl_down_sync(0xffffffffu, m, o));
        if (tid == 0) sh[0] = m;
    }
    __syncthreads();
    m = sh[0];
    __syncthreads();
    float e[4];
    float s = 0.f;
#pragma unroll
    for (int i = 0; i < 4; i++) {
        e[i] = expf(v[i] - m);
        s += e[i];
    }
#pragma unroll
    for (int o = 16; o > 0; o >>= 1)
        s += __shfl_down_sync(0xffffffffu, s, o);
    if (lane == 0) sh[w] = s;
    __syncthreads();
    if (tid < 32) {
        s = (tid < 8) ? sh[tid] : 0.f;
#pragma unroll
        for (int o = 4; o > 0; o >>= 1)
            s += __shfl_down_sync(0xffffffffu, s, o);
        if (tid == 0) sh[0] = s;
    }
    __syncthreads();
    float inv = 1.0f / sh[0];
#pragma unroll
    for (int i = 0; i < 4; i++) {
        int c = tid + i * 256;
        oh[row * C_DIM + c] = __float2half_rn(e[i] * inv);
    }
}

static void launch_gemm(const __half* A, const __half* B,
                        float* C, __half* O,
                        int M, int N, int K, int lda, int ldb, int ldc,
                        long sA, long sB, long sC, int batches,
                        const float* bias, const float* residual,
                        float scale, int act, int pe)
{
    dim3 grid(N / 128, M / 128, batches);
    gemm_fp16<<<grid, 256, SM_TOT>>>(A, B, C, O, K, lda, ldb, ldc,
                                     sA, sB, sC, bias, residual, scale, act, pe);
}

extern "C" void kernel_launch(void* const* d_in, const int* in_sizes, int n_in,
                              void* d_out, int out_size)
{
    const float* x        = (const float*)d_in[0];
    const float* fc_in_w  = (const float*)d_in[1];
    const float* fc_in_b  = (const float*)d_in[2];
    const float* ln_g     = (const float*)d_in[3];
    const float* ln_b     = (const float*)d_in[4];
    const float* qkv_w    = (const float*)d_in[5];
    const float* qkv_b    = (const float*)d_in[6];
    const float* proj_w   = (const float*)d_in[7];
    const float* proj_b   = (const float*)d_in[8];
    const float* fc_out_w = (const float*)d_in[9];
    const float* fc_out_b = (const float*)d_in[10];
    float* out = (float*)d_out;

    cudaFuncSetAttribute(gemm_fp16, cudaFuncAttributeMaxDynamicSharedMemorySize, SM_TOT);

    __half *wh, *xh, *ah, *qh, *kt, *vt, *m1, *smh;
    float *h0, *att, *pred;
    cudaGetSymbolAddress((void**)&wh, g_w_h);
    cudaGetSymbolAddress((void**)&xh, g_x_h);
    cudaGetSymbolAddress((void**)&ah, g_a_h);
    cudaGetSymbolAddress((void**)&qh, g_qkv_h);
    cudaGetSymbolAddress((void**)&kt, g_kt_h);
    cudaGetSymbolAddress((void**)&vt, g_vt_h);
    cudaGetSymbolAddress((void**)&m1, g_m1_h);
    cudaGetSymbolAddress((void**)&smh, g_sm_h);
    cudaGetSymbolAddress((void**)&h0, g_h0);
    cudaGetSymbolAddress((void**)&att, g_att);
    cudaGetSymbolAddress((void**)&pred, g_pred);

    // convert all inputs/weights to fp16 in ONE launch
    cvt5_kernel<<<1024, 256>>>(
        x, xh, (long)M_TOT * C_DIM / 4,
        fc_in_w, wh + W_FCIN, (long)C_DIM * C_DIM / 4,
        qkv_w, wh + W_QKV, (long)4 * 3 * C_DIM * C_DIM / 4,
        proj_w, wh + W_PROJ, (long)4 * C_DIM * C_DIM / 4,
        fc_out_w, wh + W_FCOUT, (long)C_DIM * C_DIM / 4);

    // h0 = x @ fc_in_w^T + fc_in_b    (fp32 out only)
    launch_gemm(xh, wh + W_FCIN, h0, nullptr,
                M_TOT, C_DIM, C_DIM, C_DIM, C_DIM, C_DIM, 0, 0, 0, 1,
                fc_in_b, nullptr, 1.0f, 0, 0);

    // a = fp16(layernorm(h0))
    layernorm_kernel<<<M_TOT, 256>>>(h0, ln_g, ln_b, ah);

    for (int i = 0; i < 4; i++) {
        long wq = W_QKV + (long)i * 3 * C_DIM * C_DIM;
        long wp = W_PROJ + (long)i * C_DIM * C_DIM;

        // qkv = fp16(gelu(a @ qkv_w[i]^T + qkv_b[i]))
        launch_gemm(ah, wh + wq, nullptr, qh,
                    M_TOT, 3 * C_DIM, C_DIM, C_DIM, C_DIM, 3 * C_DIM, 0, 0, 0, 1,
                    qkv_b + (long)i * 3 * C_DIM, nullptr, 1.0f, 1, 0);

        // kT, vT transposes (vectorized)
        transpose_h<<<dim3(S_LEN / 64, C_DIM / 64, NB), 256>>>(qh, kt, C_DIM);
        transpose_h<<<dim3(S_LEN / 64, C_DIM / 64, NB), 256>>>(qh, vt, 2 * C_DIM);

        // M1[c'][c] = sum_t v[t][c'] k[t][c]  = (k^T v)^T   (NT: A=vT, B=kT; batched)
        launch_gemm(vt, kt, nullptr, m1,
                    C_DIM, C_DIM, S_LEN, S_LEN, S_LEN, C_DIM,
                    (long)C_DIM * S_LEN, (long)C_DIM * S_LEN, (long)C_DIM * C_DIM,
                    NB, nullptr, nullptr, 1.0f, 0, 0);

        // att = q @ M1^T / 1024 = (q@k^T/C)@v   (fp32 out, batched; q strided in qkv)
        launch_gemm(qh, m1, att, nullptr,
                    S_LEN, C_DIM, C_DIM, 3 * C_DIM, C_DIM, C_DIM,
                    (long)S_LEN * 3 * C_DIM, (long)C_DIM * C_DIM, (long)S_LEN * C_DIM,
                    NB, nullptr, nullptr, 1.0f / 1024.0f, 0, 0);

        // sm = fp16(softmax(att))
        softmax_kernel<<<M_TOT, 256>>>(att, smh);

        // a = fp16(gelu(sm @ proj_w[i]^T + proj_b[i]) [+ pred]); fp32 pred copy on i==0
        launch_gemm(smh, wh + wp, (i == 0) ? pred : nullptr, ah,
                    M_TOT, C_DIM, C_DIM, C_DIM, C_DIM, C_DIM, 0, 0, 0, 1,
                    proj_b + (long)i * C_DIM, (i == 0) ? nullptr : pred, 1.0f, 1, 0);
    }

    // out = a @ fc_out_w^T + fc_out_b + pose_enc
    launch_gemm(ah, wh + W_FCOUT, out, nullptr,
                M_TOT, C_DIM, C_DIM, C_DIM, C_DIM, C_DIM, 0, 0, 0, 1,
                fc_out_b, nullptr, 1.0f, 0, 1);
}

// round 17
// speedup vs baseline: 1.1469x; 1.1469x over previous
#include <cuda_runtime.h>
#include <cuda_fp16.h>
#include <math.h>
#include <stdint.h>

#define M_TOT 8192
#define C_DIM 1024
#define S_LEN 2048
#define NB 4

// ---------------- static scratch (no allocations allowed) ----------------
// fp32
__device__ float g_h0[M_TOT * C_DIM];
__device__ float g_att[M_TOT * C_DIM];
__device__ float g_pred[M_TOT * C_DIM];
// fp16 buffers
#define W_FCIN 0
#define W_QKV  1048576
#define W_PROJ 13631488
#define W_FCOUT 17825792
#define W_TOTAL 18874368
__device__ __half g_w_h[W_TOTAL];
__device__ __half g_x_h[M_TOT * C_DIM];
__device__ __half g_a_h[M_TOT * C_DIM];
__device__ __half g_qkv_h[(long)M_TOT * 3 * C_DIM];
__device__ __half g_kt_h[(long)NB * C_DIM * S_LEN];
__device__ __half g_vt_h[(long)NB * C_DIM * S_LEN];
__device__ __half g_m1_h[(long)NB * C_DIM * C_DIM];
__device__ __half g_sm_h[M_TOT * C_DIM];

// ---------------- helpers ----------------
__device__ __forceinline__ uint32_t smem_u32(const void* p) {
    uint32_t a;
    asm("{ .reg .u64 t; cvta.to.shared.u64 t, %1; cvt.u32.u64 %0, t; }" : "=r"(a) : "l"(p));
    return a;
}
__device__ __forceinline__ float gelu_f(float x) {
    return 0.5f * x * (1.0f + erff(x * 0.70710678118654752f));
}
__device__ __forceinline__ uint32_t h2_bits(__half2 v) {
    return *reinterpret_cast<uint32_t*>(&v);
}
__device__ __forceinline__ void ldsm4(uint32_t* r, uint32_t addr) {
    asm volatile("ldmatrix.sync.aligned.m8n8.x4.shared.b16 {%0,%1,%2,%3}, [%4];"
        : "=r"(r[0]), "=r"(r[1]), "=r"(r[2]), "=r"(r[3]) : "r"(addr));
}
__device__ __forceinline__ void mma16816(float* d, const uint32_t* a, const uint32_t* b) {
    asm volatile("mma.sync.aligned.m16n8k16.row.col.f32.f16.f16.f32 "
        "{%0,%1,%2,%3}, {%4,%5,%6,%7}, {%8,%9}, {%0,%1,%2,%3};"
        : "+f"(d[0]), "+f"(d[1]), "+f"(d[2]), "+f"(d[3])
        : "r"(a[0]), "r"(a[1]), "r"(a[2]), "r"(a[3]), "r"(b[0]), "r"(b[1]));
}
#define CP16(dst, src) \
    asm volatile("cp.async.cg.shared.global [%0], [%1], 16;" :: "r"(dst), "l"(src) : "memory")
#define CP_COMMIT() asm volatile("cp.async.commit_group;" ::: "memory")
#define CP_WAIT1() asm volatile("cp.async.wait_group 1;" ::: "memory")

// SMEM stage: A tile + B tile, each 128 rows x 32 fp16, row stride 80B. 3 stages.
#define ROW_B 80
#define OFF_A 0
#define OFF_B 10240
#define STAGE_B 20480
#define SM_TOT (3 * STAGE_B)

// D[M,N] = epi(scale * A[M,K] @ B[N,K]^T), fp16 inputs, single-pass HMMA,
// 3-stage cp.async, single barrier/chunk. CTA 128x128, BK=32, 256 thr = 8 warps.
__global__ void __launch_bounds__(256, 2) gemm_fp16(
    const __half* __restrict__ A, const __half* __restrict__ B,
    float* __restrict__ C, __half* __restrict__ O,
    int K, int lda, int ldb, int ldc,
    long sA, long sB, long sC,
    const float* __restrict__ bias, const float* __restrict__ residual,
    float scale, int act, int pe)
{
    extern __shared__ char sm[];
    uint32_t sb = smem_u32(sm);

    int tid = threadIdx.x, wid = tid >> 5, lane = tid & 31;
    long bz = blockIdx.z;
    A += bz * sA; B += bz * sB;
    if (C) C += bz * sC;
    if (O) O += bz * sC;
    const float* res = residual ? residual + bz * sC : nullptr;
    long row0 = (long)blockIdx.y * 128, col0 = (long)blockIdx.x * 128;

    int wm = wid >> 2, wn = wid & 3;     // 2 x 4 warp grid
    int m0w = wm * 64, n0w = wn * 32;

    float acc[4][4][4];
#pragma unroll
    for (int i = 0; i < 4; i++)
#pragma unroll
        for (int j = 0; j < 4; j++)
#pragma unroll
            for (int e = 0; e < 4; e++) acc[i][j][e] = 0.f;

    // loader: row = tid>>1 (0..127), 16B groups sg, sg+1 of 4 per row-chunk
    const int r_ld = tid >> 1;
    const int sg = (tid & 1) * 2;
    const int NC = K >> 5;

    const __half* a_src = A + (row0 + r_ld) * lda + sg * 8;
    const __half* b_src = B + (col0 + r_ld) * ldb + sg * 8;
    const uint32_t stA = sb + OFF_A + r_ld * ROW_B + sg * 16;
    const uint32_t stB = sb + OFF_B + r_ld * ROW_B + sg * 16;

    auto issue = [&](int c, uint32_t bofs) {
        long ko = (long)c * 32;
        CP16(stA + bofs,      a_src + ko);
        CP16(stA + bofs + 16, a_src + ko + 8);
        CP16(stB + bofs,      b_src + ko);
        CP16(stB + bofs + 16, b_src + ko + 8);
    };

    // ldmatrix addresses (stage 0 base; add bofs, + ks*32 per k16 step)
    uint32_t a_addr[4], b_addr[2];
#pragma unroll
    for (int i = 0; i < 4; i++) {
        uint32_t r = m0w + i * 16 + (lane & 15);
        a_addr[i] = sb + OFF_A + r * ROW_B + (lane >> 4) * 16;
    }
#pragma unroll
    for (int jp = 0; jp < 2; jp++) {     // pair of n-tiles (2jp, 2jp+1)
        uint32_t r = n0w + jp * 16 + ((lane >> 4) << 3) + (lane & 7);
        b_addr[jp] = sb + OFF_B + r * ROW_B + ((lane >> 3) & 1) * 16;
    }

    issue(0, 0); CP_COMMIT();
    if (NC > 1) issue(1, STAGE_B);
    CP_COMMIT();

    int s0 = 0, s2 = 2;   // stage of chunk c, stage of chunk c+2
    for (int c = 0; c < NC; c++) {
        // committed so far: groups 0..c+1  ->  wait_group 1 guarantees chunk c done
        CP_WAIT1();
        __syncthreads();
        // stage s2 = (c+2)%3 = (c-1)%3: all warps passed the barrier after reading
        // chunk c-1, so overwriting it now is safe.
        if (c + 2 < NC) issue(c + 2, s2 * STAGE_B);
        CP_COMMIT();

        uint32_t bofs = s0 * STAGE_B;
#pragma unroll
        for (int ks = 0; ks < 2; ks++) {
            uint32_t ah[4][4], bh[2][4];
#pragma unroll
            for (int i = 0; i < 4; i++)
                ldsm4(ah[i], a_addr[i] + bofs + ks * 32);
#pragma unroll
            for (int jp = 0; jp < 2; jp++)
                ldsm4(bh[jp], b_addr[jp] + bofs + ks * 32);
#pragma unroll
            for (int i = 0; i < 4; i++)
#pragma unroll
                for (int j = 0; j < 4; j++)
                    mma16816(acc[i][j], ah[i], &bh[j >> 1][(j & 1) * 2]);
        }
        s0 = (s0 == 2) ? 0 : s0 + 1;
        s2 = (s2 == 2) ? 0 : s2 + 1;
    }

    // epilogue: thread holds C[r1][cc..cc+1], C[r1+8][cc..cc+1] per (i,j)
#pragma unroll
    for (int i = 0; i < 4; i++) {
        long r1 = row0 + m0w + i * 16 + (lane >> 2);
        long r2 = r1 + 8;
#pragma unroll
        for (int j = 0; j < 4; j++) {
            long cc = col0 + n0w + j * 8 + 2 * (lane & 3);
            float2 bi = bias ? *(const float2*)(bias + cc) : make_float2(0.f, 0.f);
            float v0 = acc[i][j][0] * scale + bi.x;
            float v1 = acc[i][j][1] * scale + bi.y;
            float v2 = acc[i][j][2] * scale + bi.x;
            float v3 = acc[i][j][3] * scale + bi.y;
            if (act) { v0 = gelu_f(v0); v1 = gelu_f(v1); v2 = gelu_f(v2); v3 = gelu_f(v3); }
            if (res) {
                float2 q1 = *(const float2*)(res + r1 * ldc + cc);
                float2 q2 = *(const float2*)(res + r2 * ldc + cc);
                v0 += q1.x; v1 += q1.y; v2 += q2.x; v3 += q2.y;
            }
            if (pe) {
                float d0 = expf((float)cc * (-2.0f / 1024.0f) * 6.9077552789821370521f);
                float d1 = expf((float)(cc + 1) * (-2.0f / 1024.0f) * 6.9077552789821370521f);
                int s1 = (int)(r1 & (S_LEN - 1)), sx = (int)(r2 & (S_LEN - 1));
                float a10 = s1 * d0, a11 = s1 * d1, a20 = sx * d0, a21 = sx * d1;
                v0 += (s1 & 1) ? cosf(a10) : sinf(a10);
                v1 += (s1 & 1) ? cosf(a11) : sinf(a11);
                v2 += (sx & 1) ? cosf(a20) : sinf(a20);
                v3 += (sx & 1) ? cosf(a21) : sinf(a21);
            }
            if (C) {
                *(float2*)(C + r1 * ldc + cc) = make_float2(v0, v1);
                *(float2*)(C + r2 * ldc + cc) = make_float2(v2, v3);
            }
            if (O) {
                *(uint32_t*)(O + r1 * ldc + cc) = h2_bits(__floats2half2_rn(v0, v1));
                *(uint32_t*)(O + r2 * ldc + cc) = h2_bits(__floats2half2_rn(v2, v3));
            }
        }
    }
}

// fused fp32 -> fp16 convert of 5 tensors, grid-stride over float4s
__global__ void cvt5_kernel(const float* s0, __half* d0, long n0,
                            const float* s1, __half* d1, long n1,
                            const float* s2, __half* d2, long n2,
                            const float* s3, __half* d3, long n3,
                            const float* s4, __half* d4, long n4)
{
    long tot = n0 + n1 + n2 + n3 + n4;
    long i = (long)blockIdx.x * blockDim.x + threadIdx.x;
    long stride = (long)gridDim.x * blockDim.x;
    for (; i < tot; i += stride) {
        const float* s; __half* d; long k = i;
        if (k < n0) { s = s0; d = d0; }
        else if ((k -= n0) < n1) { s = s1; d = d1; }
        else if ((k -= n1) < n2) { s = s2; d = d2; }
        else if ((k -= n2) < n3) { s = s3; d = d3; }
        else { k -= n3; s = s4; d = d4; }
        float4 f = ((const float4*)s)[k];
        uint2 h;
        h.x = h2_bits(__floats2half2_rn(f.x, f.y));
        h.y = h2_bits(__floats2half2_rn(f.z, f.w));
        ((uint2*)d)[k] = h;
    }
}

// dst[b][c][s] = qkv[b, s, co + c], vectorized 64x64 tile (uint4 both sides)
__global__ void transpose_h(const __half* __restrict__ q,
                            __half* __restrict__ dst_, int co)
{
    __shared__ __half t[64][65];
    int b = blockIdx.z;
    int s0 = blockIdx.x * 64, c0 = blockIdx.y * 64;
    int r = threadIdx.x >> 3;      // 0..31
    int g = threadIdx.x & 7;       // 0..7 (8-half group)
    const __half* src = q + (long)b * S_LEN * 3 * C_DIM + co;
#pragma unroll
    for (int rr = r; rr < 64; rr += 32) {
        uint4 v = *(const uint4*)(src + (long)(s0 + rr) * (3 * C_DIM) + c0 + g * 8);
        __half tmp[8];
        *(uint4*)tmp = v;
#pragma unroll
        for (int e = 0; e < 8; e++) t[rr][g * 8 + e] = tmp[e];
    }
    __syncthreads();
    __half* dst = dst_ + (long)b * C_DIM * S_LEN;
#pragma unroll
    for (int rr = r; rr < 64; rr += 32) {   // c index
        __half tmp[8];
#pragma unroll
        for (int e = 0; e < 8; e++) tmp[e] = t[g * 8 + e][rr];
        *(uint4*)(dst + (long)(c0 + rr) * S_LEN + s0 + g * 8) = *(uint4*)tmp;
    }
}

// layernorm over last dim (1024), fp32 in -> fp16 out
__global__ void layernorm_kernel(const float* __restrict__ h,
                                 const float* __restrict__ g,
                                 const float* __restrict__ b,
                                 __half* __restrict__ oh)
{
    __shared__ float sa[8], sb2[8];
    long row = blockIdx.x;
    const float* p = h + row * C_DIM;
    int tid = threadIdx.x;
    float v[4];
    float s1 = 0.f, s2 = 0.f;
#pragma unroll
    for (int i = 0; i < 4; i++) {
        v[i] = p[tid + i * 256];
        s1 += v[i];
        s2 += v[i] * v[i];
    }
#pragma unroll
    for (int o = 16; o > 0; o >>= 1) {
        s1 += __shfl_down_sync(0xffffffffu, s1, o);
        s2 += __shfl_down_sync(0xffffffffu, s2, o);
    }
    int lane = tid & 31, w = tid >> 5;
    if (lane == 0) { sa[w] = s1; sb2[w] = s2; }
    __syncthreads();
    if (tid < 32) {
        s1 = (tid < 8) ? sa[tid] : 0.f;
        s2 = (tid < 8) ? sb2[tid] : 0.f;
#pragma unroll
        for (int o = 4; o > 0; o >>= 1) {
            s1 += __shfl_down_sync(0xffffffffu, s1, o);
            s2 += __shfl_down_sync(0xffffffffu, s2, o);
        }
        if (tid == 0) { sa[0] = s1; sb2[0] = s2; }
    }
    __syncthreads();
    float mu = sa[0] * (1.0f / 1024.0f);
    float var = sb2[0] * (1.0f / 1024.0f) - mu * mu;
    float inv = rsqrtf(var + 1e-5f);
#pragma unroll
    for (int i = 0; i < 4; i++) {
        int c = tid + i * 256;
        float y = (v[i] - mu) * inv * g[c] + b[c];
        oh[row * C_DIM + c] = __float2half_rn(y);
    }
}

// softmax over last dim (1024), fp32 in -> fp16 out
__global__ void softmax_kernel(const float* __restrict__ att,
                               __half* __restrict__ oh)
{
    __shared__ float sh[8];
    long row = blockIdx.x;
    const float* p = att + row * C_DIM;
    int tid = threadIdx.x;
    float v[4];
    float m = -INFINITY;
#pragma unroll
    for (int i = 0; i < 4; i++) {
        v[i] = p[tid + i * 256];
        m = fmaxf(m, v[i]);
    }
#pragma unroll
    for (int o = 16; o > 0; o >>= 1)
        m = fmaxf(m, __shfl_down_sync(0xffffffffu, m, o));
    int lane = tid & 31, w = tid >> 5;
    if (lane == 0) sh[w] = m;
    __syncthreads();
    if (tid < 32) {
        m = (tid < 8) ? sh[tid] : -INFINITY;
#pragma unroll
        for (int o = 4; o > 0; o >>= 1)
            m = fmaxf(m, __shfl_down_sync(0xffffffffu, m, o));
        if (tid == 0) sh[0] = m;
    }
    __syncthreads();
    m = sh[0];
    __syncthreads();
    float e[4];
    float s = 0.f;
#pragma unroll
    for (int i = 0; i < 4; i++) {
        e[i] = expf(v[i] - m);
        s += e[i];
    }
#pragma unroll
    for (int o = 16; o > 0; o >>= 1)
        s += __shfl_down_sync(0xffffffffu, s, o);
    if (lane == 0) sh[w] = s;
    __syncthreads();
    if (tid < 32) {
        s = (tid < 8) ? sh[tid] : 0.f;
#pragma unroll
        for (int o = 4; o > 0; o >>= 1)
            s += __shfl_down_sync(0xffffffffu, s, o);
        if (tid == 0) sh[0] = s;
    }
    __syncthreads();
    float inv = 1.0f / sh[0];
#pragma unroll
    for (int i = 0; i < 4; i++) {
        int c = tid + i * 256;
        oh[row * C_DIM + c] = __float2half_rn(e[i] * inv);
    }
}

static void launch_gemm(const __half* A, const __half* B,
                        float* C, __half* O,
                        int M, int N, int K, int lda, int ldb, int ldc,
                        long sA, long sB, long sC, int batches,
                        const float* bias, const float* residual,
                        float scale, int act, int pe)
{
    dim3 grid(N / 128, M / 128, batches);
    gemm_fp16<<<grid, 256, SM_TOT>>>(A, B, C, O, K, lda, ldb, ldc,
                                     sA, sB, sC, bias, residual, scale, act, pe);
}

extern "C" void kernel_launch(void* const* d_in, const int* in_sizes, int n_in,
                              void* d_out, int out_size)
{
    const float* x        = (const float*)d_in[0];
    const float* fc_in_w  = (const float*)d_in[1];
    const float* fc_in_b  = (const float*)d_in[2];
    const float* ln_g     = (const float*)d_in[3];
    const float* ln_b     = (const float*)d_in[4];
    const float* qkv_w    = (const float*)d_in[5];
    const float* qkv_b    = (const float*)d_in[6];
    const float* proj_w   = (const float*)d_in[7];
    const float* proj_b   = (const float*)d_in[8];
    const float* fc_out_w = (const float*)d_in[9];
    const float* fc_out_b = (const float*)d_in[10];
    float* out = (float*)d_out;

    cudaFuncSetAttribute(gemm_fp16, cudaFuncAttributeMaxDynamicSharedMemorySize, SM_TOT);

    __half *wh, *xh, *ah, *qh, *kt, *vt, *m1, *smh;
    float *h0, *att, *pred;
    cudaGetSymbolAddress((void**)&wh, g_w_h);
    cudaGetSymbolAddress((void**)&xh, g_x_h);
    cudaGetSymbolAddress((void**)&ah, g_a_h);
    cudaGetSymbolAddress((void**)&qh, g_qkv_h);
    cudaGetSymbolAddress((void**)&kt, g_kt_h);
    cudaGetSymbolAddress((void**)&vt, g_vt_h);
    cudaGetSymbolAddress((void**)&m1, g_m1_h);
    cudaGetSymbolAddress((void**)&smh, g_sm_h);
    cudaGetSymbolAddress((void**)&h0, g_h0);
    cudaGetSymbolAddress((void**)&att, g_att);
    cudaGetSymbolAddress((void**)&pred, g_pred);

    // convert all inputs/weights to fp16 in ONE launch
    cvt5_kernel<<<1024, 256>>>(
        x, xh, (long)M_TOT * C_DIM / 4,
        fc_in_w, wh + W_FCIN, (long)C_DIM * C_DIM / 4,
        qkv_w, wh + W_QKV, (long)4 * 3 * C_DIM * C_DIM / 4,
        proj_w, wh + W_PROJ, (long)4 * C_DIM * C_DIM / 4,
        fc_out_w, wh + W_FCOUT, (long)C_DIM * C_DIM / 4);

    // h0 = x @ fc_in_w^T + fc_in_b    (fp32 out only)
    launch_gemm(xh, wh + W_FCIN, h0, nullptr,
                M_TOT, C_DIM, C_DIM, C_DIM, C_DIM, C_DIM, 0, 0, 0, 1,
                fc_in_b, nullptr, 1.0f, 0, 0);

    // a = fp16(layernorm(h0))
    layernorm_kernel<<<M_TOT, 256>>>(h0, ln_g, ln_b, ah);

    for (int i = 0; i < 4; i++) {
        long wq = W_QKV + (long)i * 3 * C_DIM * C_DIM;
        long wp = W_PROJ + (long)i * C_DIM * C_DIM;

        // qkv = fp16(gelu(a @ qkv_w[i]^T + qkv_b[i]))
        launch_gemm(ah, wh + wq, nullptr, qh,
                    M_TOT, 3 * C_DIM, C_DIM, C_DIM, C_DIM, 3 * C_DIM, 0, 0, 0, 1,
                    qkv_b + (long)i * 3 * C_DIM, nullptr, 1.0f, 1, 0);

        // kT, vT transposes (vectorized)
        transpose_h<<<dim3(S_LEN / 64, C_DIM / 64, NB), 256>>>(qh, kt, C_DIM);
        transpose_h<<<dim3(S_LEN / 64, C_DIM / 64, NB), 256>>>(qh, vt, 2 * C_DIM);

        // M1[c'][c] = sum_t v[t][c'] k[t][c]  = (k^T v)^T   (NT: A=vT, B=kT; batched)
        launch_gemm(vt, kt, nullptr, m1,
                    C_DIM, C_DIM, S_LEN, S_LEN, S_LEN, C_DIM,
                    (long)C_DIM * S_LEN, (long)C_DIM * S_LEN, (long)C_DIM * C_DIM,
                    NB, nullptr, nullptr, 1.0f, 0, 0);

        // att = q @ M1^T / 1024 = (q@k^T/C)@v   (fp32 out, batched; q strided in qkv)
        launch_gemm(qh, m1, att, nullptr,
                    S_LEN, C_DIM, C_DIM, 3 * C_DIM, C_DIM, C_DIM,
                    (long)S_LEN * 3 * C_DIM, (long)C_DIM * C_DIM, (long)S_LEN * C_DIM,
                    NB, nullptr, nullptr, 1.0f / 1024.0f, 0, 0);

        // sm = fp16(softmax(att))
        softmax_kernel<<<M_TOT, 256>>>(att, smh);

        // a = fp16(gelu(sm @ proj_w[i]^T + proj_b[i]) [+ pred]); fp32 pred copy on i==0
        launch_gemm(smh, wh + wp, (i == 0) ? pred : nullptr, ah,
                    M_TOT, C_DIM, C_DIM, C_DIM, C_DIM, C_DIM, 0, 0, 0, 1,
                    proj_b + (long)i * C_DIM, (i == 0) ? nullptr : pred, 1.0f, 1, 0);
    }

    // out = a @ fc_out_w^T + fc_out_b + pose_enc
    launch_gemm(ah, wh + W_FCOUT, out, nullptr,
                M_TOT, C_DIM, C_DIM, C_DIM, C_DIM, C_DIM, 0, 0, 0, 1,
                fc_out_b, nullptr, 1.0f, 0, 1);
}